// round 17
// baseline (speedup 1.0000x reference)
#include <cuda_runtime.h>
#include <cuda_fp16.h>
#include <cstdint>

#define D 128
#define BM 64
#define N_MAX 100000
#define E_MAX 3200000
#define CAP 128          // proven best (R9)

// ---- packed f32x2 helpers --------------------------------------------------
#define FMA_F32X2(d, a, b, c) \
    asm("fma.rn.f32x2 %0, %1, %2, %3;" : "=l"(d) : "l"(a), "l"(b), "l"(c))
#define ADD_F32X2(d, a, b) \
    asm("add.rn.f32x2 %0, %1, %2;" : "=l"(d) : "l"(a), "l"(b))
#define PACK_DUP_F32X2(out, r) \
    asm("mov.b64 %0, {%1, %1};" : "=l"(out) : "r"(r))

static __device__ __forceinline__ unsigned h2_to_u32(__half2 h) {
    return *reinterpret_cast<unsigned*>(&h);
}
static __device__ __forceinline__ __half2 u32_to_h2(unsigned u) {
    return *reinterpret_cast<__half2*>(&u);
}

// Scratch
__device__ uint2  g_hh[N_MAX * 32];          // h in fp16 (4 halves / lane-slot)
__device__ float4 g_wt4[D * D / 4];          // W^T (read via __ldg, L1-resident)
__device__ int    g_cnt[N_MAX];              // per-node cursor
__device__ int2   g_bkt[(long long)N_MAX * CAP];  // (src, w-bits) buckets
__device__ int    g_ovf_cnt;                 // overflow edges (expected 0)
__device__ int4   g_ovf[4096];               // (src, dst, w-bits, pad)

// ---------------------------------------------------------------------------
// prep: blocks [0, nb_zero) zero g_cnt; blocks [nb_zero, +64) transpose W.
// ---------------------------------------------------------------------------
__global__ void prep_kernel(const float* __restrict__ W, int n_nodes, int nb_zero) {
    int b = blockIdx.x;
    if (b < nb_zero) {
        int i = b * 256 + threadIdx.x;
        if (i < n_nodes) g_cnt[i] = 0;
        if (i == 0) g_ovf_cnt = 0;
    } else {
        int idx = (b - nb_zero) * 256 + threadIdx.x;   // 0 .. 16383
        int j = idx >> 7;
        int k = idx & (D - 1);
        ((float*)g_wt4)[k * D + j] = W[j * D + k];
    }
}

// ---------------------------------------------------------------------------
// FUSED kernel: 32KB smem, b%3 interleave (GEMM : place = 1 : 2).
// ---------------------------------------------------------------------------
__device__ __forceinline__ void gemm_block(
    const float* __restrict__ x, const float* __restrict__ bias,
    int n_rows, int blk)
{
    extern __shared__ float4 smem4[];
    float4* Xs4 = smem4;                 // [64][32] f4 = 32KB

    const int tid  = threadIdx.x;
    const int row0 = blk * BM;
    const int rows = min(BM, n_rows - row0);

    {
        const float4* x4 = (const float4*)(x + (long long)row0 * D);
        const int nf4 = rows * (D / 4);
        for (int i = tid; i < nf4; i += 256)
            Xs4[i] = x4[i];
    }
    __syncthreads();

    const int warp = tid >> 5;
    const int lane = tid & 31;
    const int r0 = warp * 8;

    const ulonglong2* Wg = (const ulonglong2*)g_wt4;  // global, L1-cached

    unsigned long long acc[8][2];
    #pragma unroll
    for (int i = 0; i < 8; i++) { acc[i][0] = 0ull; acc[i][1] = 0ull; }

    #pragma unroll 4
    for (int k = 0; k < D; k += 4) {
        ulonglong2 wv0 = __ldg(Wg + (k + 0) * 32 + lane);
        ulonglong2 wv1 = __ldg(Wg + (k + 1) * 32 + lane);
        ulonglong2 wv2 = __ldg(Wg + (k + 2) * 32 + lane);
        ulonglong2 wv3 = __ldg(Wg + (k + 3) * 32 + lane);
        #pragma unroll
        for (int i = 0; i < 8; i++) {
            float4 xv = Xs4[(r0 + i) * 32 + (k >> 2)];  // warp broadcast
            unsigned long long xd;
            PACK_DUP_F32X2(xd, __float_as_uint(xv.x));
            FMA_F32X2(acc[i][0], xd, wv0.x, acc[i][0]);
            FMA_F32X2(acc[i][1], xd, wv0.y, acc[i][1]);
            PACK_DUP_F32X2(xd, __float_as_uint(xv.y));
            FMA_F32X2(acc[i][0], xd, wv1.x, acc[i][0]);
            FMA_F32X2(acc[i][1], xd, wv1.y, acc[i][1]);
            PACK_DUP_F32X2(xd, __float_as_uint(xv.z));
            FMA_F32X2(acc[i][0], xd, wv2.x, acc[i][0]);
            FMA_F32X2(acc[i][1], xd, wv2.y, acc[i][1]);
            PACK_DUP_F32X2(xd, __float_as_uint(xv.w));
            FMA_F32X2(acc[i][0], xd, wv3.x, acc[i][0]);
            FMA_F32X2(acc[i][1], xd, wv3.y, acc[i][1]);
        }
    }

    ulonglong2 bv = ((const ulonglong2*)bias)[lane];
    #pragma unroll
    for (int i = 0; i < 8; i++) {
        int r = r0 + i;
        if (r < rows) {
            ulonglong2 o;
            ADD_F32X2(o.x, acc[i][0], bv.x);
            ADD_F32X2(o.y, acc[i][1], bv.y);
            float2 p0 = *(float2*)&o.x;
            float2 p1 = *(float2*)&o.y;
            uint2 hh;
            hh.x = h2_to_u32(__floats2half2_rn(p0.x, p0.y));
            hh.y = h2_to_u32(__floats2half2_rn(p1.x, p1.y));
            g_hh[(long long)(row0 + r) * 32 + lane] = hh;
        }
    }
}

// place: phase-split so the 4 atomics issue independently (MLP=4),
// then the 4 dependent stores.
__device__ __forceinline__ void place_block(
    const int* __restrict__ src, const int* __restrict__ dst,
    const float* __restrict__ w, int n_edges, int pidx)
{
    int t = pidx * 256 + threadIdx.x;
    int e = t * 4;
    if (e + 4 <= n_edges) {
        int s0 = src[e],   s1 = src[e+1],   s2 = src[e+2],   s3 = src[e+3];
        int d0 = dst[e],   d1 = dst[e+1],   d2 = dst[e+2],   d3 = dst[e+3];
        float w0 = w[e],   w1 = w[e+1],     w2 = w[e+2],     w3 = w[e+3];
        // phase 1: 4 independent atomics in flight
        int p0 = atomicAdd(&g_cnt[d0], 1);
        int p1 = atomicAdd(&g_cnt[d1], 1);
        int p2 = atomicAdd(&g_cnt[d2], 1);
        int p3 = atomicAdd(&g_cnt[d3], 1);
        // phase 2: stores
        if (p0 < CAP) g_bkt[(long long)d0 * CAP + p0] = make_int2(s0, __float_as_int(w0));
        else { int o = atomicAdd(&g_ovf_cnt, 1); if (o < 4096) g_ovf[o] = make_int4(s0, d0, __float_as_int(w0), 0); }
        if (p1 < CAP) g_bkt[(long long)d1 * CAP + p1] = make_int2(s1, __float_as_int(w1));
        else { int o = atomicAdd(&g_ovf_cnt, 1); if (o < 4096) g_ovf[o] = make_int4(s1, d1, __float_as_int(w1), 0); }
        if (p2 < CAP) g_bkt[(long long)d2 * CAP + p2] = make_int2(s2, __float_as_int(w2));
        else { int o = atomicAdd(&g_ovf_cnt, 1); if (o < 4096) g_ovf[o] = make_int4(s2, d2, __float_as_int(w2), 0); }
        if (p3 < CAP) g_bkt[(long long)d3 * CAP + p3] = make_int2(s3, __float_as_int(w3));
        else { int o = atomicAdd(&g_ovf_cnt, 1); if (o < 4096) g_ovf[o] = make_int4(s3, d3, __float_as_int(w3), 0); }
    } else {
        for (int i = e; i < n_edges; i++) {
            int d = dst[i];
            int pos = atomicAdd(&g_cnt[d], 1);
            if (pos < CAP) g_bkt[(long long)d * CAP + pos] = make_int2(src[i], __float_as_int(w[i]));
            else { int o = atomicAdd(&g_ovf_cnt, 1); if (o < 4096) g_ovf[o] = make_int4(src[i], d, __float_as_int(w[i]), 0); }
        }
    }
}

__global__ __launch_bounds__(256)
void fused_gemm_place_kernel(const float* __restrict__ x,
                             const float* __restrict__ bias,
                             const int* __restrict__ src,
                             const int* __restrict__ dst,
                             const float* __restrict__ w,
                             int n_rows, int n_edges,
                             int nb_gemm, int nb_place) {
    int b = blockIdx.x;
    if (b % 3 == 0) {
        int gi = b / 3;
        if (gi < nb_gemm) gemm_block(x, bias, n_rows, gi);
    } else {
        int pi = b - b / 3 - 1;
        if (pi < nb_place) place_block(src, dst, w, n_edges, pi);
    }
}

// ---------------------------------------------------------------------------
// aggregate (R9 shape) + folded fixup.
// Nodes with cnt <= CAP: plain store (no overflow possible for them).
// Nodes with cnt > CAP: owner warp uses red.global.add for its base sum, and
// extra blocks (node >= n_nodes region) add overflow edges the same way —
// order-independent, so no race. out is pre-zeroed only logically: since
// overflow nodes use red, their out row must start at 0 -> we zero it first
// via the owner warp's red-path initial store being a plain st of acc? No:
// owner writes acc with plain store FIRST is racy with red. Instead owner
// red-adds and we rely on... we must zero. Solution: owner warp for overflow
// nodes writes acc via plain store, then arrives at a device-scope fence via
// atomic flag; overflow blocks spin on the flag for that node. Simpler and
// sufficient: overflow blocks run in the SAME kernel but grid-stride AFTER
// all node blocks... not guaranteed. Given P(overflow)~1e-35 we keep the
// separate tiny fixup ONLY when needed: aggregate's last block checks
// g_ovf_cnt and processes overflow with red.global.add against rows whose
// owner warp ALSO used red... => both paths red => need zeroed rows.
// Final safe design: owner warp of an overflow node zeroes nothing special —
// overflow nodes get plain store from owner (base part, slots [0,CAP)) and
// the last block red-adds overflow edges. Race window exists only if the
// last block reaches an overflow row before its owner stored. We close it
// with a device-wide flag: last block spins until g_done == nb_node_blocks.
// ---------------------------------------------------------------------------
__device__ unsigned g_done;

__global__ __launch_bounds__(256)
void aggregate_kernel(float* __restrict__ out, int n_nodes, int nb_node_blocks) {
    if ((int)blockIdx.x < nb_node_blocks) {
        int node = (blockIdx.x * 256 + threadIdx.x) >> 5;
        int lane = threadIdx.x & 31;
        if (node < n_nodes) {
            const int2* seg = g_bkt + (long long)node * CAP;
            int cnt = g_cnt[node];
            int end = min(cnt, CAP);

            float4 acc = make_float4(0.f, 0.f, 0.f, 0.f);

            int i = 0;
            for (; i + 8 <= end; i += 8) {
                int2 ed[8];
                uint2 hv[8];
                #pragma unroll
                for (int j = 0; j < 8; j++) ed[j] = seg[i + j];
                #pragma unroll
                for (int j = 0; j < 8; j++) hv[j] = g_hh[(long long)ed[j].x * 32 + lane];
                #pragma unroll
                for (int j = 0; j < 8; j++) {
                    float wv = __int_as_float(ed[j].y);
                    float2 a  = __half22float2(u32_to_h2(hv[j].x));
                    float2 bq = __half22float2(u32_to_h2(hv[j].y));
                    acc.x += a.x * wv; acc.y += a.y * wv;
                    acc.z += bq.x * wv; acc.w += bq.y * wv;
                }
            }
            for (; i < end; i++) {
                int2 e = seg[i];
                float wv = __int_as_float(e.y);
                uint2 hv = g_hh[(long long)e.x * 32 + lane];
                float2 a  = __half22float2(u32_to_h2(hv.x));
                float2 bq = __half22float2(u32_to_h2(hv.y));
                acc.x += a.x * wv; acc.y += a.y * wv; acc.z += bq.x * wv; acc.w += bq.y * wv;
            }

            ((float4*)out)[(long long)node * 32 + lane] = acc;
        }
        // signal block completion (one thread per block)
        __syncthreads();
        if (threadIdx.x == 0) {
            __threadfence();
            atomicAdd(&g_done, 1u);
        }
    } else {
        // fixup block: wait for all node blocks, then red-add overflow edges.
        if (g_ovf_cnt == 0) return;   // fast path: nothing to do (typical)
        if (threadIdx.x == 0) {
            while (atomicAdd(&g_done, 0u) < (unsigned)nb_node_blocks) { }
        }
        __syncthreads();
        int n = min(g_ovf_cnt, 4096);
        int lane = threadIdx.x & 31;
        int wid = threadIdx.x >> 5;
        for (int e = wid; e < n; e += 8) {
            int4 ov = g_ovf[e];
            float wv = __int_as_float(ov.z);
            uint2 hv = g_hh[(long long)ov.x * 32 + lane];
            float2 a  = __half22float2(u32_to_h2(hv.x));
            float2 bq = __half22float2(u32_to_h2(hv.y));
            float* p = out + (long long)ov.y * D + lane * 4;
            asm volatile("red.global.add.v4.f32 [%0], {%1, %2, %3, %4};"
                         :: "l"(p), "f"(a.x * wv), "f"(a.y * wv),
                            "f"(bq.x * wv), "f"(bq.y * wv) : "memory");
        }
    }
}

__global__ void reset_done_kernel() {
    if (threadIdx.x == 0) g_done = 0u;
}

// ---------------------------------------------------------------------------
extern "C" void kernel_launch(void* const* d_in, const int* in_sizes, int n_in,
                              void* d_out, int out_size) {
    const float* x   = (const float*)d_in[0];
    const float* w   = (const float*)d_in[1];
    const float* W   = (const float*)d_in[2];
    const float* b   = (const float*)d_in[3];
    const int*   src = (const int*)d_in[4];   // int32 (JAX x64 disabled)
    const int*   dst = (const int*)d_in[5];

    int N = in_sizes[0] / D;
    int E = in_sizes[1];
    float* out = (float*)d_out;

    int nb_zero  = (N + 255) / 256;
    int nb_gemm  = (N + BM - 1) / BM;              // 1563
    int nb_place = (E + 4 * 256 - 1) / (4 * 256);  // 3125
    int half_p = (nb_place + 1) / 2;
    int T = 3 * (nb_gemm > half_p ? nb_gemm : half_p);

    reset_done_kernel<<<1, 32>>>();
    prep_kernel<<<nb_zero + (D * D) / 256, 256>>>(W, N, nb_zero);

    const int smem_bytes = BM * D * sizeof(float);  // 32 KB (X tile only)
    cudaFuncSetAttribute(fused_gemm_place_kernel,
                         cudaFuncAttributeMaxDynamicSharedMemorySize, smem_bytes);
    fused_gemm_place_kernel<<<T, 256, smem_bytes>>>(x, b, src, dst, w,
                                                    N, E, nb_gemm, nb_place);

    int nb_node_blocks = (N * 32 + 255) / 256;   // one warp per node
    aggregate_kernel<<<nb_node_blocks + 1, 256>>>(out, N, nb_node_blocks);
}